// round 2
// baseline (speedup 1.0000x reference)
#include <cuda_runtime.h>
#include <math_constants.h>

#define N_TOKENS (16*8192)
#define HD    256
#define NEXP  32
#define BATCH 16
#define SEQ   8192
#define TPB   256
#define NBLK  (N_TOKENS/TPB)   // 512, 32 blocks per batch row (aligned)

// Global accumulators for aux loss (per batch, per expert). Zeroed each call.
__device__ float g_ssum[BATCH*NEXP];
__device__ int   g_cnt [BATCH*NEXP];

__device__ __forceinline__ void ffma2(unsigned long long& d,
                                      unsigned long long a,
                                      unsigned long long b) {
    // packed 2xfp32 FMA (Blackwell f32x2) — d = a*b + d, lanewise on 32-bit halves
    asm("fma.rn.f32x2 %0, %1, %2, %3;" : "=l"(d) : "l"(a), "l"(b), "l"(d));
}

__global__ void zero_kernel() {
    int i = threadIdx.x;
    if (i < BATCH*NEXP) { g_ssum[i] = 0.0f; g_cnt[i] = 0; }
}

__global__ void __launch_bounds__(TPB, 2)
gate_kernel(const float* __restrict__ hs, const float* __restrict__ w,
            float* __restrict__ out)
{
    __shared__ float ws[NEXP*HD];           // 32 KB weight tile
    __shared__ float s_ssum[TPB/32][NEXP];  // per-warp expert score sums
    __shared__ int   s_cnt[NEXP];

    const int tid  = threadIdx.x;
    const int lane = tid & 31;
    const int warp = tid >> 5;

    // Stage weight into smem (coalesced float4)
    {
        const float4* w4  = (const float4*)w;
        float4*       ws4 = (float4*)ws;
        #pragma unroll
        for (int i = tid; i < NEXP*HD/4; i += TPB) ws4[i] = w4[i];
    }
    if (tid < NEXP) s_cnt[tid] = 0;
    __syncthreads();

    const long long t = (long long)blockIdx.x * TPB + tid;
    const ulonglong2* xr = (const ulonglong2*)(hs + (size_t)t * HD);

    unsigned long long acc[NEXP];
    #pragma unroll
    for (int e = 0; e < NEXP; e++) acc[e] = 0ull;

    // Main GEMV loop: 64 chunks of 4 floats (two f32x2 pairs)
    ulonglong2 xv = xr[0];
    #pragma unroll 4
    for (int c = 0; c < HD/4; c++) {
        ulonglong2 xn = xv;
        if (c + 1 < HD/4) xn = xr[c + 1];      // prefetch next x chunk
        const char* wp = (const char*)ws + c * 16;
        #pragma unroll
        for (int e = 0; e < NEXP; e++) {
            // broadcast smem read (uniform address across warp) of packed pairs
            ulonglong2 wv = *(const ulonglong2*)(wp + e * (HD * 4));
            ffma2(acc[e], xv.x, wv.x);
            ffma2(acc[e], xv.y, wv.y);
        }
        xv = xn;
    }

    // acc -> logits, find max (== best logit; argmax with lowest-index tiebreak)
    float logit[NEXP];
    #pragma unroll
    for (int e = 0; e < NEXP; e++) {
        float lo = __uint_as_float((unsigned)(acc[e] & 0xffffffffu));
        float hi = __uint_as_float((unsigned)(acc[e] >> 32));
        logit[e] = lo + hi;
    }
    int best = 0;
    float mx = logit[0];
    #pragma unroll
    for (int e = 1; e < NEXP; e++)
        if (logit[e] > mx) { mx = logit[e]; best = e; }

    // softmax (best score = exp(0)/sum = 1/sum)
    float sc[NEXP];
    float ssum = 0.0f;
    #pragma unroll
    for (int e = 0; e < NEXP; e++) { sc[e] = expf(logit[e] - mx); ssum += sc[e]; }
    const float inv = 1.0f / ssum;
    #pragma unroll
    for (int e = 0; e < NEXP; e++) sc[e] *= inv;

    // Outputs: [idx as float | topk_weight | aux]
    out[t]            = (float)best;
    out[N_TOKENS + t] = inv;   // max score, SCALING = 1.0

    // per-block expert selection counts (addresses well spread -> cheap)
    atomicAdd(&s_cnt[best], 1);

    // Warp transpose-reduce: after 5 stages, sc[0] on lane L = sum over the
    // warp's 32 tokens of score[expert=L]. 31 shuffles + 31 adds total.
    #pragma unroll
    for (int m = 16; m >= 1; m >>= 1) {
        #pragma unroll
        for (int i = 0; i < m; i++) {
            float send = (lane & m) ? sc[i] : sc[i + m];
            float recv = __shfl_xor_sync(0xffffffffu, send, m);
            sc[i] = ((lane & m) ? sc[i + m] : sc[i]) + recv;
        }
    }
    s_ssum[warp][lane] = sc[0];
    __syncthreads();

    if (tid < NEXP) {
        float s = 0.0f;
        #pragma unroll
        for (int wd = 0; wd < TPB/32; wd++) s += s_ssum[wd][tid];
        const int b = (int)(((long long)blockIdx.x * TPB) / SEQ);
        atomicAdd(&g_ssum[b*NEXP + tid], s);
        atomicAdd(&g_cnt [b*NEXP + tid], s_cnt[tid]);
    }
}

__global__ void finalize_kernel(float* __restrict__ out) {
    __shared__ float red[BATCH*NEXP];
    const int i = threadIdx.x;  // 512 threads == BATCH*NEXP
    // ce = cnt/(SEQ*K/E) = cnt/256 ; mean score over seq = ssum/SEQ
    float term = ((float)g_cnt[i] * (1.0f/256.0f)) * (g_ssum[i] * (1.0f/(float)SEQ));
    red[i] = term;
    __syncthreads();
    #pragma unroll
    for (int s = (BATCH*NEXP)/2; s > 0; s >>= 1) {
        if (i < s) red[i] += red[i + s];
        __syncthreads();
    }
    if (i == 0) out[2*N_TOKENS] = red[0] * (0.001f / 16.0f);  // alpha * mean over batch
}

extern "C" void kernel_launch(void* const* d_in, const int* in_sizes, int n_in,
                              void* d_out, int out_size) {
    const float* hs = (const float*)d_in[0];
    const float* w  = (const float*)d_in[1];
    float* out = (float*)d_out;
    zero_kernel<<<1, BATCH*NEXP>>>();
    gate_kernel<<<NBLK, TPB>>>(hs, w, out);
    finalize_kernel<<<1, BATCH*NEXP>>>(out);
}

// round 3
// speedup vs baseline: 1.2312x; 1.2312x over previous
#include <cuda_runtime.h>

#define N_TOKENS (16*8192)
#define HD       256
#define NEXP     32
#define BATCH    16
#define SEQ      8192
#define TPB      256            // 8 warps
#define TOK_PER_WARP 8
#define TOK_PER_BLOCK (TPB/32*TOK_PER_WARP)   // 64
#define NBLK     (N_TOKENS/TOK_PER_BLOCK)     // 2048
#define WS_STRIDE 260           // floats per expert row in smem (4-way-max conflict, 16B aligned)
#define CHUNK    64             // k elements per pipeline chunk
#define NCHUNK   (HD/CHUNK)     // 4
#define TILE_BYTES (TOK_PER_WARP*CHUNK*4)     // 2048 per warp per buffer

// global accumulators (zero-initialized at load; last block resets them each call)
__device__ float g_ssum[BATCH*NEXP];
__device__ int   g_cnt [BATCH*NEXP];
__device__ unsigned g_done;

__device__ __forceinline__ void ffma2(unsigned long long& d,
                                      unsigned long long a,
                                      unsigned long long b) {
    asm("fma.rn.f32x2 %0, %1, %2, %3;" : "=l"(d) : "l"(a), "l"(b), "l"(d));
}
__device__ __forceinline__ unsigned smem_u32(const void* p) {
    return (unsigned)__cvta_generic_to_shared(p);
}
__device__ __forceinline__ void cp_async16(unsigned dst, const void* src) {
    asm volatile("cp.async.cg.shared.global [%0], [%1], 16;\n" :: "r"(dst), "l"(src));
}
__device__ __forceinline__ void cp_commit() {
    asm volatile("cp.async.commit_group;\n");
}
template<int N> __device__ __forceinline__ void cp_wait() {
    asm volatile("cp.async.wait_group %0;\n" :: "n"(N));
}
__device__ __forceinline__ unsigned f2sortable(float v) {
    unsigned u = __float_as_uint(v);
    return (u & 0x80000000u) ? ~u : (u | 0x80000000u);
}

extern __shared__ char smem_raw[];
// layout: ws[NEXP*WS_STRIDE] floats | tiles: 8 warps x 2 bufs x TILE_BYTES
#define WS_BYTES (NEXP*WS_STRIDE*4)

__global__ void __launch_bounds__(TPB, 2)
gate_kernel(const float* __restrict__ hs, const float* __restrict__ w,
            float* __restrict__ out)
{
    float* ws = (float*)smem_raw;
    __shared__ float s_aux[NEXP];
    __shared__ int   s_cnt[NEXP];
    __shared__ int   s_last;

    const int tid  = threadIdx.x;
    const int lane = tid & 31;
    const int warp = tid >> 5;

    // stage gate weight into smem: ws[e*WS_STRIDE + k] = w[e*256 + k]
    #pragma unroll
    for (int i = tid; i < NEXP*HD; i += TPB) {
        int e = i >> 8, k = i & 255;
        ws[e*WS_STRIDE + k] = w[i];
    }
    if (tid < NEXP) { s_aux[tid] = 0.0f; s_cnt[tid] = 0; }
    __syncthreads();

    const int  tb0 = (blockIdx.x * (TPB/32) + warp) * TOK_PER_WARP; // warp's first token
    const int  b   = tb0 >> 13;                                     // batch row
    char* tile0 = smem_raw + WS_BYTES + (warp*2    )*TILE_BYTES;
    char* tile1 = smem_raw + WS_BYTES + (warp*2 + 1)*TILE_BYTES;

    // ---- stage chunk 0 ----
    {
        unsigned dst = smem_u32(tile0);
        #pragma unroll
        for (int it = 0; it < 4; it++) {
            int u = it*32 + lane;            // 16B unit index within 2KB tile
            int r = u >> 4, q = u & 15;      // token row, 16B col
            cp_async16(dst + u*16, hs + (size_t)(tb0 + r)*HD + q*4);
        }
        cp_commit();
    }

    unsigned long long acc[TOK_PER_WARP];
    #pragma unroll
    for (int t = 0; t < TOK_PER_WARP; t++) acc[t] = 0ull;

    const float* wrow = ws + lane * WS_STRIDE;   // this lane's expert row

    for (int c = 0; c < NCHUNK; c++) {
        char* cur = (c & 1) ? tile1 : tile0;
        // prefetch chunk c+1
        if (c + 1 < NCHUNK) {
            char* nxt = (c & 1) ? tile0 : tile1;
            unsigned dst = smem_u32(nxt);
            const float* src = hs + (c+1)*CHUNK;
            #pragma unroll
            for (int it = 0; it < 4; it++) {
                int u = it*32 + lane;
                int r = u >> 4, q = u & 15;
                cp_async16(dst + u*16, src + (size_t)(tb0 + r)*HD + q*4);
            }
            cp_commit();
            cp_wait<1>();
        } else {
            cp_wait<0>();
        }
        __syncwarp();

        // load this chunk's weight slice into registers: 32 packed pairs
        unsigned long long w2[CHUNK/2];
        #pragma unroll
        for (int m = 0; m < CHUNK/4; m++) {
            ulonglong2 wv = *(const ulonglong2*)(wrow + c*CHUNK + m*4);
            w2[2*m]   = wv.x;
            w2[2*m+1] = wv.y;
        }

        // compute: 4-token interleave, split dependent ffma2 phases
        #pragma unroll
        for (int tg = 0; tg < TOK_PER_WARP; tg += 4) {
            #pragma unroll
            for (int kc = 0; kc < CHUNK/4; kc++) {
                ulonglong2 xv[4];
                #pragma unroll
                for (int j = 0; j < 4; j++)
                    xv[j] = *(const ulonglong2*)(cur + ((tg+j)*CHUNK + kc*4)*4);
                #pragma unroll
                for (int j = 0; j < 4; j++) ffma2(acc[tg+j], xv[j].x, w2[2*kc]);
                #pragma unroll
                for (int j = 0; j < 4; j++) ffma2(acc[tg+j], xv[j].y, w2[2*kc+1]);
            }
        }
        __syncwarp();
    }

    // ---- epilogue: per-token softmax/argmax across lanes (lane = expert) ----
    float aux_acc = 0.0f;
    int   cnt_acc = 0;
    float my_idx = 0.0f, my_w = 0.0f;

    #pragma unroll
    for (int t = 0; t < TOK_PER_WARP; t++) {
        float v = __uint_as_float((unsigned)(acc[t] & 0xffffffffu))
                + __uint_as_float((unsigned)(acc[t] >> 32));
        unsigned u = f2sortable(v);
        unsigned m = __reduce_max_sync(0xffffffffu, u);
        unsigned msk = __ballot_sync(0xffffffffu, u == m);
        int amax = __ffs(msk) - 1;                 // lowest expert index on ties
        float vmax = __shfl_sync(0xffffffffu, v, amax);
        float e = expf(v - vmax);
        float s = e;
        #pragma unroll
        for (int d = 16; d >= 1; d >>= 1) s += __shfl_xor_sync(0xffffffffu, s, d);
        float inv = 1.0f / s;
        aux_acc += e * inv;
        cnt_acc += (lane == amax);
        if (lane == t) { my_idx = (float)amax; my_w = inv; }
    }
    if (lane < TOK_PER_WARP) {
        out[tb0 + lane]            = my_idx;
        out[N_TOKENS + tb0 + lane] = my_w;
    }

    // block-level aux reduction, then one global atomic set per block
    atomicAdd(&s_aux[lane], aux_acc);
    atomicAdd(&s_cnt[lane], cnt_acc);
    __syncthreads();
    if (tid < NEXP) {
        atomicAdd(&g_ssum[b*NEXP + tid], s_aux[tid]);
        atomicAdd(&g_cnt [b*NEXP + tid], s_cnt[tid]);
    }

    // ---- last block computes aux loss and resets globals ----
    if (tid == 0) {
        __threadfence();
        unsigned ticket = atomicAdd(&g_done, 1u);
        s_last = (ticket == (unsigned)(gridDim.x - 1));
    }
    __syncthreads();
    if (s_last) {
        __threadfence();
        __shared__ float red[TPB];
        float term = 0.0f;
        #pragma unroll
        for (int i = tid; i < BATCH*NEXP; i += TPB)
            term += ((float)g_cnt[i] * (1.0f/256.0f)) * (g_ssum[i] * (1.0f/(float)SEQ));
        red[tid] = term;
        __syncthreads();
        #pragma unroll
        for (int s2 = TPB/2; s2 > 0; s2 >>= 1) {
            if (tid < s2) red[tid] += red[tid + s2];
            __syncthreads();
        }
        if (tid == 0) out[2*N_TOKENS] = red[0] * (0.001f / (float)BATCH);
        // reset for next graph replay
        #pragma unroll
        for (int i = tid; i < BATCH*NEXP; i += TPB) { g_ssum[i] = 0.0f; g_cnt[i] = 0; }
        if (tid == 0) g_done = 0u;
    }
}

extern "C" void kernel_launch(void* const* d_in, const int* in_sizes, int n_in,
                              void* d_out, int out_size) {
    const float* hs = (const float*)d_in[0];
    const float* w  = (const float*)d_in[1];
    float* out = (float*)d_out;
    const int smem = WS_BYTES + (TPB/32)*2*TILE_BYTES;  // ~65.5 KB
    static int attr_done = 0;
    // idempotent attribute set (host-side, not captured; same every call)
    cudaFuncSetAttribute(gate_kernel, cudaFuncAttributeMaxDynamicSharedMemorySize, smem);
    (void)attr_done;
    gate_kernel<<<NBLK, TPB, smem>>>(hs, w, out);
}

// round 5
// speedup vs baseline: 1.7299x; 1.4051x over previous
#include <cuda_runtime.h>

#define N_TOKENS (16*8192)
#define HD       256
#define NEXP     32
#define BATCH    16
#define SEQ      8192
#define TPB      256
#define WARPS    (TPB/32)                   // 8
#define TOK_PER_WARP 32
#define TOK_PER_BLOCK (WARPS*TOK_PER_WARP)  // 256
#define NBLK     (N_TOKENS/TOK_PER_BLOCK)   // 512
#define CHUNK    32                         // k-floats per pipeline chunk
#define NCHUNK   (HD/CHUNK)                 // 8
#define K4PC     (CHUNK/4)                  // 8 granules per chunk
#define WG       66                         // weight row stride, 16B granules (!= 0 mod 8 in groups of 4)
#define XG       9                          // x row stride in granules (≡1 mod 8 -> conflict-free)
#define WS_GRAN  (NEXP*WG)                  // 2112 granules = 33792 B
#define XTILE_GRAN (TOK_PER_WARP*XG)        // 288 granules = 4608 B
#define XTILE_BYTES (XTILE_GRAN*16)
#define SMEM_DYN (WS_GRAN*16 + WARPS*2*XTILE_BYTES)   // 33792 + 73728 = 107520 B

__device__ float g_ssum[BATCH*NEXP];
__device__ int   g_cnt [BATCH*NEXP];
__device__ unsigned g_done;

__device__ __forceinline__ void ffma2(unsigned long long& d,
                                      unsigned long long a,
                                      unsigned long long b) {
    asm("fma.rn.f32x2 %0, %1, %2, %3;" : "=l"(d) : "l"(a), "l"(b), "l"(d));
}
__device__ __forceinline__ unsigned smem_u32(const void* p) {
    return (unsigned)__cvta_generic_to_shared(p);
}
__device__ __forceinline__ void cp_async16(unsigned dst, const void* src) {
    asm volatile("cp.async.cg.shared.global [%0], [%1], 16;\n" :: "r"(dst), "l"(src));
}
__device__ __forceinline__ void cp_commit() {
    asm volatile("cp.async.commit_group;\n");
}
template<int N> __device__ __forceinline__ void cp_wait() {
    asm volatile("cp.async.wait_group %0;\n" :: "n"(N));
}

extern __shared__ char smem_raw[];

__global__ void __launch_bounds__(TPB, 2)
gate_kernel(const float* __restrict__ hs, const float* __restrict__ w,
            float* __restrict__ out)
{
    char* ws = smem_raw;                     // weights, padded granule layout
    __shared__ float s_aux[NEXP];
    __shared__ int   s_cnt[NEXP];
    __shared__ int   s_last;

    const int tid  = threadIdx.x;
    const int lane = tid & 31;
    const int warp = tid >> 5;
    const int eg   = lane & 3;               // expert interleave group
    const int tg   = lane >> 2;              // token interleave group (0..7)

    // stage weights into padded smem: granule (e*WG + k4) <- w[e*256 + k4*4 ..]
    {
        const float4* w4 = (const float4*)w;
        #pragma unroll
        for (int i = tid; i < NEXP*HD/4; i += TPB) {
            int e = i >> 6, k4 = i & 63;
            *(float4*)(ws + (e*WG + k4)*16) = w4[i];
        }
    }
    if (tid < NEXP) { s_aux[tid] = 0.0f; s_cnt[tid] = 0; }
    __syncthreads();

    const int tb0 = (blockIdx.x * WARPS + warp) * TOK_PER_WARP;  // warp's first token
    const int b   = blockIdx.x >> 5;                             // batch row (256 tok/blk, 32 blk/row)
    char* tile[2] = { smem_raw + WS_GRAN*16 + (warp*2  )*XTILE_BYTES,
                      smem_raw + WS_GRAN*16 + (warp*2+1)*XTILE_BYTES };

    // ---- stage chunk 0 (32 tokens x 32 floats, padded rows) ----
    {
        unsigned dst = smem_u32(tile[0]);
        #pragma unroll
        for (int it = 0; it < 8; it++) {
            int u = it*32 + lane;            // 16B unit
            int t = u >> 3, k4 = u & 7;
            cp_async16(dst + (t*XG + k4)*16, hs + (size_t)(tb0 + t)*HD + k4*4);
        }
        cp_commit();
    }

    unsigned long long acc[8][4];            // [expert j][token i], k-split f32x2
    #pragma unroll
    for (int j = 0; j < 8; j++)
        #pragma unroll
        for (int i = 0; i < 4; i++) acc[j][i] = 0ull;

    for (int c = 0; c < NCHUNK; c++) {
        char* cur = tile[c & 1];
        if (c + 1 < NCHUNK) {
            unsigned dst = smem_u32(tile[(c+1) & 1]);
            const float* src = hs + (c+1)*CHUNK;
            #pragma unroll
            for (int it = 0; it < 8; it++) {
                int u = it*32 + lane;
                int t = u >> 3, k4 = u & 7;
                cp_async16(dst + (t*XG + k4)*16, src + (size_t)(tb0 + t)*HD + k4*4);
            }
            cp_commit();
            cp_wait<1>();
        } else {
            cp_wait<0>();
        }
        __syncwarp();

        #pragma unroll
        for (int k4 = 0; k4 < K4PC; k4++) {
            ulonglong2 xv[4];
            #pragma unroll
            for (int i = 0; i < 4; i++)      // 8 distinct token rows / inst, 1 wf
                xv[i] = *(const ulonglong2*)(cur + ((i*8 + tg)*XG + k4)*16);
            #pragma unroll
            for (int j = 0; j < 8; j++) {    // 4 distinct expert rows / inst, 1 wf
                ulonglong2 wv = *(const ulonglong2*)(ws + (((j<<2) + eg)*WG + c*K4PC + k4)*16);
                #pragma unroll
                for (int i = 0; i < 4; i++) ffma2(acc[j][i], xv[i].x, wv.x);
                #pragma unroll
                for (int i = 0; i < 4; i++) ffma2(acc[j][i], xv[i].y, wv.y);
            }
        }
        __syncwarp();
    }

    // ---- epilogue: lane holds experts {4j+eg} x tokens {8i+tg} ----
    float aux_local[8];
    #pragma unroll
    for (int j = 0; j < 8; j++) aux_local[j] = 0.0f;

    #pragma unroll
    for (int i = 0; i < 4; i++) {
        float lg[8];
        #pragma unroll
        for (int j = 0; j < 8; j++)
            lg[j] = __uint_as_float((unsigned)(acc[j][i] & 0xffffffffu))
                  + __uint_as_float((unsigned)(acc[j][i] >> 32));
        // local argmax over this lane's 8 experts
        float m = lg[0]; int a = eg;
        #pragma unroll
        for (int j = 1; j < 8; j++) {
            int e = (j<<2) + eg;
            if (lg[j] > m) { m = lg[j]; a = e; }
        }
        // combine across the 4 eg-lanes of this token (xor 1,2), lowest-idx ties
        #pragma unroll
        for (int d = 1; d <= 2; d <<= 1) {
            float om = __shfl_xor_sync(0xffffffffu, m, d);
            int   oa = __shfl_xor_sync(0xffffffffu, a, d);
            if (om > m || (om == m && oa < a)) { m = om; a = oa; }
        }
        // softmax pieces
        float ex[8]; float s = 0.0f;
        #pragma unroll
        for (int j = 0; j < 8; j++) { ex[j] = expf(lg[j] - m); s += ex[j]; }
        #pragma unroll
        for (int d = 1; d <= 2; d <<= 1) s += __shfl_xor_sync(0xffffffffu, s, d);
        float inv = 1.0f / s;
        #pragma unroll
        for (int j = 0; j < 8; j++) aux_local[j] += ex[j] * inv;
        if (eg == 0) {
            int g = tb0 + i*8 + tg;
            out[g]            = (float)a;
            out[N_TOKENS + g] = inv;         // top score = exp(0)/sum
            atomicAdd(&s_cnt[a], 1);
        }
    }

    // reduce aux over token-groups (lanes sharing eg): xor 4,8,16
    #pragma unroll
    for (int j = 0; j < 8; j++) {
        float v = aux_local[j];
        #pragma unroll
        for (int d = 4; d <= 16; d <<= 1) v += __shfl_xor_sync(0xffffffffu, v, d);
        if (tg == 0) atomicAdd(&s_aux[(j<<2) + eg], v);
    }
    __syncthreads();
    if (tid < NEXP) {
        atomicAdd(&g_ssum[b*NEXP + tid], s_aux[tid]);
        atomicAdd(&g_cnt [b*NEXP + tid], s_cnt[tid]);
    }

    // ---- last block: finalize aux loss, reset globals ----
    if (tid == 0) {
        __threadfence();
        unsigned ticket = atomicAdd(&g_done, 1u);
        s_last = (ticket == (unsigned)(gridDim.x - 1));
    }
    __syncthreads();
    if (s_last) {
        __threadfence();
        __shared__ float red[TPB];
        float term = 0.0f;
        #pragma unroll
        for (int i = tid; i < BATCH*NEXP; i += TPB)
            term += ((float)g_cnt[i] * (1.0f/256.0f)) * (g_ssum[i] * (1.0f/(float)SEQ));
        red[tid] = term;
        __syncthreads();
        #pragma unroll
        for (int s2 = TPB/2; s2 > 0; s2 >>= 1) {
            if (tid < s2) red[tid] += red[tid + s2];
            __syncthreads();
        }
        if (tid == 0) out[2*N_TOKENS] = red[0] * (0.001f / (float)BATCH);
        #pragma unroll
        for (int i = tid; i < BATCH*NEXP; i += TPB) { g_ssum[i] = 0.0f; g_cnt[i] = 0; }
        if (tid == 0) g_done = 0u;
    }
}

extern "C" void kernel_launch(void* const* d_in, const int* in_sizes, int n_in,
                              void* d_out, int out_size) {
    const float* hs = (const float*)d_in[0];
    const float* w  = (const float*)d_in[1];
    float* out = (float*)d_out;
    cudaFuncSetAttribute(gate_kernel, cudaFuncAttributeMaxDynamicSharedMemorySize, SMEM_DYN);
    gate_kernel<<<NBLK, TPB, SMEM_DYN>>>(hs, w, out);
}

// round 7
// speedup vs baseline: 1.9506x; 1.1276x over previous
#include <cuda_runtime.h>

#define N_TOKENS (16*8192)
#define HD       256
#define NEXP     32
#define BATCH    16
#define SEQ      8192
#define TPB      256
#define WARPS    (TPB/32)                   // 8
#define TOK_PER_WARP 32
#define TOK_PER_BLOCK (WARPS*TOK_PER_WARP)  // 256
#define NBLK     (N_TOKENS/TOK_PER_BLOCK)   // 512
#define CHUNK    32                         // k-floats per pipeline chunk
#define NCHUNK   (HD/CHUNK)                 // 8
#define K4PC     (CHUNK/4)                  // 8 granules per chunk
#define XG       9                          // x row stride in 16B granules (≡1 mod 8 -> conflict-free)
#define WT_BYTES (HD*NEXP*4)                // 32768 transposed weights
#define XTILE_BYTES (TOK_PER_WARP*XG*16)    // 4608
#define SMEM_DYN (WT_BYTES + WARPS*2*XTILE_BYTES)   // 32768 + 73728 = 106496 B

__device__ float g_ssum[BATCH*NEXP];
__device__ int   g_cnt [BATCH*NEXP];
__device__ unsigned g_done;

__device__ __forceinline__ void ffma2(unsigned long long& d,
                                      unsigned long long a,
                                      unsigned long long b) {
    asm("fma.rn.f32x2 %0, %1, %2, %3;" : "=l"(d) : "l"(a), "l"(b), "l"(d));
}
__device__ __forceinline__ unsigned long long dup2(float v) {
    unsigned long long r;
    asm("mov.b64 %0, {%1, %1};" : "=l"(r) : "f"(v));
    return r;
}
__device__ __forceinline__ unsigned smem_u32(const void* p) {
    return (unsigned)__cvta_generic_to_shared(p);
}
__device__ __forceinline__ void cp_async16(unsigned dst, const void* src) {
    asm volatile("cp.async.cg.shared.global [%0], [%1], 16;\n" :: "r"(dst), "l"(src));
}
__device__ __forceinline__ void cp_commit() {
    asm volatile("cp.async.commit_group;\n");
}
template<int N> __device__ __forceinline__ void cp_wait() {
    asm volatile("cp.async.wait_group %0;\n" :: "n"(N));
}

extern __shared__ char smem_raw[];

__global__ void __launch_bounds__(TPB, 2)
gate_kernel(const float* __restrict__ hs, const float* __restrict__ w,
            float* __restrict__ out)
{
    float* wT = (float*)smem_raw;            // wT[k*32 + e], 32 KB
    char* xarea = smem_raw + WT_BYTES;
    __shared__ float s_aux[NEXP];
    __shared__ int   s_cnt[NEXP];
    __shared__ int   s_last;

    const int tid  = threadIdx.x;
    const int lane = tid & 31;
    const int warp = tid >> 5;
    const int tg   = lane & 7;               // token interleave group (0..7)
    const int eg   = lane >> 3;              // expert group (0..3) -> experts eg*8..eg*8+7

    // ---- stage transposed weights via conflict-free bounce (uses x-tile area as temp) ----
    {
        float* wtmp = (float*)xarea;         // row-major, row stride 257 (odd -> conflict-free)
        #pragma unroll
        for (int i = tid; i < NEXP*HD; i += TPB)
            wtmp[(i >> 8)*257 + (i & 255)] = w[i];
        __syncthreads();
        #pragma unroll
        for (int i = tid; i < NEXP*HD; i += TPB) {
            int e = i & 31, k = i >> 5;      // lane == e -> STS conflict-free; LDS (e*257+k)%32 = (e+k)%32 ok
            wT[k*32 + e] = wtmp[e*257 + k];
        }
    }
    if (tid < NEXP) { s_aux[tid] = 0.0f; s_cnt[tid] = 0; }
    __syncthreads();                          // temp area now reusable as x tiles

    const int tb0 = (blockIdx.x * WARPS + warp) * TOK_PER_WARP;
    const int b   = blockIdx.x >> 5;          // batch row (256 tok/blk, 32 blk/row)
    char* tile[2] = { xarea + (warp*2    )*XTILE_BYTES,
                      xarea + (warp*2 + 1)*XTILE_BYTES };

    // ---- stage chunk 0 (32 tokens x 32 floats, padded rows) ----
    {
        unsigned dst = smem_u32(tile[0]);
        #pragma unroll
        for (int it = 0; it < 8; it++) {
            int u = it*32 + lane;            // 16B unit
            int t = u >> 3, k4 = u & 7;
            cp_async16(dst + (t*XG + k4)*16, hs + (size_t)(tb0 + t)*HD + k4*4);
        }
        cp_commit();
    }

    // acc[token i][expert-pair p]: halves = experts (eg*8+2p, eg*8+2p+1)
    unsigned long long acc[4][4];
    #pragma unroll
    for (int i = 0; i < 4; i++)
        #pragma unroll
        for (int p = 0; p < 4; p++) acc[i][p] = 0ull;

    for (int c = 0; c < NCHUNK; c++) {
        char* cur = tile[c & 1];
        if (c + 1 < NCHUNK) {
            unsigned dst = smem_u32(tile[(c+1) & 1]);
            const float* src = hs + (c+1)*CHUNK;
            #pragma unroll
            for (int it = 0; it < 8; it++) {
                int u = it*32 + lane;
                int t = u >> 3, k4 = u & 7;
                cp_async16(dst + (t*XG + k4)*16, src + (size_t)(tb0 + t)*HD + k4*4);
            }
            cp_commit();
            cp_wait<1>();
        } else {
            cp_wait<0>();
        }
        __syncwarp();

        #pragma unroll
        for (int k4 = 0; k4 < K4PC; k4++) {
            // 4 token rows' x granules: 8 distinct rows across tg, 4-way eg broadcast -> 1 wf each
            float4 xv[4];
            #pragma unroll
            for (int i = 0; i < 4; i++)
                xv[i] = *(const float4*)(cur + ((i*8 + tg)*XG + k4)*16);
            #pragma unroll
            for (int kk = 0; kk < 4; kk++) {
                const int k = c*CHUNK + k4*4 + kk;
                // 8 experts' weights at this k: granules {eg*2, eg*2+1} -> conflict-free
                ulonglong2 wvA = *(const ulonglong2*)(wT + k*32 + eg*8);      // experts +0..+3
                ulonglong2 wvB = *(const ulonglong2*)(wT + k*32 + eg*8 + 4);  // experts +4..+7
                #pragma unroll
                for (int i = 0; i < 4; i++) {
                    const float xs = (kk == 0) ? xv[i].x : (kk == 1) ? xv[i].y
                                   : (kk == 2) ? xv[i].z : xv[i].w;
                    unsigned long long ax = dup2(xs);
                    ffma2(acc[i][0], ax, wvA.x);
                    ffma2(acc[i][1], ax, wvA.y);
                    ffma2(acc[i][2], ax, wvB.x);
                    ffma2(acc[i][3], ax, wvB.y);
                }
            }
        }
        __syncwarp();
    }

    // ---- epilogue: lane holds tokens {8i+tg} x experts {eg*8..eg*8+7} ----
    float aux_local[8];
    #pragma unroll
    for (int j = 0; j < 8; j++) aux_local[j] = 0.0f;

    #pragma unroll
    for (int i = 0; i < 4; i++) {
        float lg[8];
        #pragma unroll
        for (int p = 0; p < 4; p++) {
            lg[2*p]   = __uint_as_float((unsigned)(acc[i][p] & 0xffffffffu));
            lg[2*p+1] = __uint_as_float((unsigned)(acc[i][p] >> 32));
        }
        // local argmax over this lane's 8 experts (contiguous ids -> lowest-index ties)
        float m = lg[0]; int a = eg*8;
        #pragma unroll
        for (int j = 1; j < 8; j++)
            if (lg[j] > m) { m = lg[j]; a = eg*8 + j; }
        // combine across the 4 eg-lanes of this token (xor 8,16), lowest-idx ties
        #pragma unroll
        for (int d = 8; d <= 16; d <<= 1) {
            float om = __shfl_xor_sync(0xffffffffu, m, d);
            int   oa = __shfl_xor_sync(0xffffffffu, a, d);
            if (om > m || (om == m && oa < a)) { m = om; a = oa; }
        }
        float ex[8]; float s = 0.0f;
        #pragma unroll
        for (int j = 0; j < 8; j++) { ex[j] = expf(lg[j] - m); s += ex[j]; }
        #pragma unroll
        for (int d = 8; d <= 16; d <<= 1) s += __shfl_xor_sync(0xffffffffu, s, d);
        float inv = 1.0f / s;
        #pragma unroll
        for (int j = 0; j < 8; j++) aux_local[j] += ex[j] * inv;
        if (eg == 0) {
            int g = tb0 + i*8 + tg;
            out[g]            = (float)a;
            out[N_TOKENS + g] = inv;          // top score = exp(0)/sum
            atomicAdd(&s_cnt[a], 1);
        }
    }

    // reduce aux over token-groups (lanes sharing eg): xor 1,2,4
    #pragma unroll
    for (int j = 0; j < 8; j++) {
        float v = aux_local[j];
        #pragma unroll
        for (int d = 1; d <= 4; d <<= 1) v += __shfl_xor_sync(0xffffffffu, v, d);
        if (tg == 0) atomicAdd(&s_aux[eg*8 + j], v);
    }
    __syncthreads();
    if (tid < NEXP) {
        atomicAdd(&g_ssum[b*NEXP + tid], s_aux[tid]);
        atomicAdd(&g_cnt [b*NEXP + tid], s_cnt[tid]);
    }

    // ---- last block: finalize aux loss, reset globals ----
    if (tid == 0) {
        __threadfence();
        unsigned ticket = atomicAdd(&g_done, 1u);
        s_last = (ticket == (unsigned)(gridDim.x - 1));
    }
    __syncthreads();
    if (s_last) {
        __threadfence();
        __shared__ float red[TPB];
        float term = 0.0f;
        #pragma unroll
        for (int i = tid; i < BATCH*NEXP; i += TPB)
            term += ((float)g_cnt[i] * (1.0f/256.0f)) * (g_ssum[i] * (1.0f/(float)SEQ));
        red[tid] = term;
        __syncthreads();
        #pragma unroll
        for (int s2 = TPB/2; s2 > 0; s2 >>= 1) {
            if (tid < s2) red[tid] += red[tid + s2];
            __syncthreads();
        }
        if (tid == 0) out[2*N_TOKENS] = red[0] * (0.001f / (float)BATCH);
        #pragma unroll
        for (int i = tid; i < BATCH*NEXP; i += TPB) { g_ssum[i] = 0.0f; g_cnt[i] = 0; }
        if (tid == 0) g_done = 0u;
    }
}

extern "C" void kernel_launch(void* const* d_in, const int* in_sizes, int n_in,
                              void* d_out, int out_size) {
    const float* hs = (const float*)d_in[0];
    const float* w  = (const float*)d_in[1];
    float* out = (float*)d_out;
    cudaFuncSetAttribute(gate_kernel, cudaFuncAttributeMaxDynamicSharedMemorySize, SMEM_DYN);
    gate_kernel<<<NBLK, TPB, SMEM_DYN>>>(hs, w, out);
}

// round 9
// speedup vs baseline: 2.2571x; 1.1571x over previous
#include <cuda_runtime.h>
#include <cstdint>

#define N_TOKENS (16*8192)
#define HD       256
#define NEXP     32
#define BATCH    16
#define SEQ      8192
#define TPB      256
#define WARPS    8
#define TOK_PER_WARP 32
#define TOK_PER_TILE 256
#define TILES_PER_CTA 2
#define TOK_PER_CTA (TOK_PER_TILE*TILES_PER_CTA)   // 512
#define NBLK     (N_TOKENS/TOK_PER_CTA)            // 256
#define NKS      (HD/8)                            // 32 k-steps
// B fragment table: [ks 32][nt 4][split 2][lane 32][r 2] u32 = 64 KB
#define BT_IDX(ks,nt,s,t,r) (((((ks)*4+(nt))*2+(s))*32+(t))*2+(r))
#define SMEM_DYN (NKS*4*2*32*2*4)

__device__ float g_ssum[BATCH*NEXP];
__device__ int   g_cnt [BATCH*NEXP];
__device__ unsigned g_done;

__device__ __forceinline__ uint32_t tf32_hi(float x) {
    uint32_t r; asm("cvt.rna.tf32.f32 %0, %1;" : "=r"(r) : "f"(x)); return r;
}
__device__ __forceinline__ void mma_tf32(float* c,
        uint32_t a0, uint32_t a1, uint32_t a2, uint32_t a3,
        uint32_t b0, uint32_t b1) {
    asm volatile(
        "mma.sync.aligned.m16n8k8.row.col.f32.tf32.tf32.f32 "
        "{%0,%1,%2,%3}, {%4,%5,%6,%7}, {%8,%9}, {%0,%1,%2,%3};"
        : "+f"(c[0]), "+f"(c[1]), "+f"(c[2]), "+f"(c[3])
        : "r"(a0), "r"(a1), "r"(a2), "r"(a3), "r"(b0), "r"(b1));
}

extern __shared__ uint32_t Btab[];

__global__ void __launch_bounds__(TPB, 2)
gate_kernel(const float* __restrict__ hs, const float* __restrict__ w,
            float* __restrict__ out)
{
    __shared__ float s_aux[NEXP];
    __shared__ int   s_cnt[NEXP];
    __shared__ int   s_last;

    const int tid  = threadIdx.x;
    const int lane = tid & 31;
    const int warp = tid >> 5;
    const int lq   = lane & 3;     // quad col
    const int lr   = lane >> 2;    // quad row (0..7)
    const int b    = blockIdx.x >> 4;   // 16 blocks (512 tok) per batch row

    // ---- build B fragment table (hi/lo tf32, k-permuted to match A loads) ----
    // logical frag col c holds physical k = 8*ks + 2c (+1 for the c+4 slot)
    #pragma unroll 4
    for (int it = 0; it < NEXP; it++) {
        float v = w[it*HD + tid];          // n = it, k = tid (coalesced)
        uint32_t hi = tf32_hi(v);
        float lo = v - __uint_as_float(hi);
        int k = tid, n = it;
        int ks = k >> 3, kk = k & 7;
        int c = kk >> 1, r = kk & 1;
        int nt = n >> 3, t = (n & 7)*4 + c;
        Btab[BT_IDX(ks, nt, 0, t, r)] = hi;
        Btab[BT_IDX(ks, nt, 1, t, r)] = __float_as_uint(lo);
    }
    if (tid < NEXP) { s_aux[tid] = 0.0f; s_cnt[tid] = 0; }
    __syncthreads();

    float aux8[8];
    #pragma unroll
    for (int i = 0; i < 8; i++) aux8[i] = 0.0f;

    for (int tile = 0; tile < TILES_PER_CTA; tile++) {
        const int tb = blockIdx.x*TOK_PER_CTA + tile*TOK_PER_TILE + warp*TOK_PER_WARP;
        // row pointers for this thread's 4 fragment rows (pre-offset by quad col)
        const float2* rp[4];
        #pragma unroll
        for (int i = 0; i < 4; i++)
            rp[i] = (const float2*)(hs + (size_t)(tb + i*8 + lr)*HD) + lq;

        float acc[2][4][4];
        #pragma unroll
        for (int mt = 0; mt < 2; mt++)
            #pragma unroll
            for (int nt = 0; nt < 4; nt++)
                #pragma unroll
                for (int i = 0; i < 4; i++) acc[mt][nt][i] = 0.0f;

        #pragma unroll 2
        for (int g = 0; g < NKS/4; g++) {
            // batch A loads for 4 k-steps: 16 LDG.64, full-line coverage
            float2 av[4][4];                 // [kstep][row]
            #pragma unroll
            for (int kk = 0; kk < 4; kk++)
                #pragma unroll
                for (int i = 0; i < 4; i++)
                    av[kk][i] = rp[i][(g*4 + kk)*4];

            #pragma unroll
            for (int kk = 0; kk < 4; kk++) {
                const int ks = g*4 + kk;
                // split A: hi via cvt, lo raw (HW-truncated to tf32)
                uint32_t ah[4][2], al[4][2];
                #pragma unroll
                for (int i = 0; i < 4; i++) {
                    ah[i][0] = tf32_hi(av[kk][i].x);
                    ah[i][1] = tf32_hi(av[kk][i].y);
                    al[i][0] = __float_as_uint(av[kk][i].x - __uint_as_float(ah[i][0]));
                    al[i][1] = __float_as_uint(av[kk][i].y - __uint_as_float(ah[i][1]));
                }
                #pragma unroll
                for (int nt = 0; nt < 4; nt++) {
                    uint2 bh = *(const uint2*)&Btab[BT_IDX(ks, nt, 0, lane, 0)];
                    uint2 bl = *(const uint2*)&Btab[BT_IDX(ks, nt, 1, lane, 0)];
                    #pragma unroll
                    for (int mt = 0; mt < 2; mt++) {
                        const int r0 = mt*2, r1 = mt*2 + 1;
                        mma_tf32(acc[mt][nt], ah[r0][0], ah[r1][0], ah[r0][1], ah[r1][1], bh.x, bh.y);
                        mma_tf32(acc[mt][nt], ah[r0][0], ah[r1][0], ah[r0][1], ah[r1][1], bl.x, bl.y);
                        mma_tf32(acc[mt][nt], al[r0][0], al[r1][0], al[r0][1], al[r1][1], bh.x, bh.y);
                    }
                }
            }
        }

        // ---- epilogue: token row (mt*16 + half*8 + lr) logits on quad (lq=0..3) ----
        #pragma unroll
        for (int mt = 0; mt < 2; mt++) {
            #pragma unroll
            for (int half = 0; half < 2; half++) {
                float lg[8];
                #pragma unroll
                for (int nt = 0; nt < 4; nt++) {
                    lg[nt*2]   = acc[mt][nt][half*2];
                    lg[nt*2+1] = acc[mt][nt][half*2+1];
                }
                // local argmax (expert ids ascending within thread)
                float m = lg[0]; int a = lq*2;
                #pragma unroll
                for (int i = 1; i < 8; i++) {
                    int e = (i>>1)*8 + lq*2 + (i&1);
                    if (lg[i] > m) { m = lg[i]; a = e; }
                }
                // combine across quad, lowest-index ties
                #pragma unroll
                for (int d = 1; d <= 2; d <<= 1) {
                    float om = __shfl_xor_sync(0xffffffffu, m, d);
                    int   oa = __shfl_xor_sync(0xffffffffu, a, d);
                    if (om > m || (om == m && oa < a)) { m = om; a = oa; }
                }
                float ex[8]; float s = 0.0f;
                #pragma unroll
                for (int i = 0; i < 8; i++) { ex[i] = expf(lg[i] - m); s += ex[i]; }
                #pragma unroll
                for (int d = 1; d <= 2; d <<= 1) s += __shfl_xor_sync(0xffffffffu, s, d);
                float inv = 1.0f / s;
                #pragma unroll
                for (int i = 0; i < 8; i++) aux8[i] += ex[i] * inv;
                if (lq == 0) {
                    int gidx = tb + mt*16 + half*8 + lr;
                    out[gidx]            = (float)a;
                    out[N_TOKENS + gidx] = inv;      // top-1 score, SCALING=1
                    atomicAdd(&s_cnt[a], 1);
                }
            }
        }
    }

    // aux: reduce across lanes with same lq (xor 4,8,16), then smem atomics
    #pragma unroll
    for (int i = 0; i < 8; i++) {
        float v = aux8[i];
        #pragma unroll
        for (int d = 4; d <= 16; d <<= 1) v += __shfl_xor_sync(0xffffffffu, v, d);
        if (lane < 4) atomicAdd(&s_aux[(i>>1)*8 + lane*2 + (i&1)], v);
    }
    __syncthreads();
    if (tid < NEXP) {
        atomicAdd(&g_ssum[b*NEXP + tid], s_aux[tid]);
        atomicAdd(&g_cnt [b*NEXP + tid], s_cnt[tid]);
    }

    // ---- last block: finalize aux loss, reset globals ----
    if (tid == 0) {
        __threadfence();
        unsigned ticket = atomicAdd(&g_done, 1u);
        s_last = (ticket == (unsigned)(gridDim.x - 1));
    }
    __syncthreads();
    if (s_last) {
        __threadfence();
        __shared__ float red[TPB];
        float term = 0.0f;
        #pragma unroll
        for (int i = tid; i < BATCH*NEXP; i += TPB)
            term += ((float)g_cnt[i] * (1.0f/256.0f)) * (g_ssum[i] * (1.0f/(float)SEQ));
        red[tid] = term;
        __syncthreads();
        #pragma unroll
        for (int s2 = TPB/2; s2 > 0; s2 >>= 1) {
            if (tid < s2) red[tid] += red[tid + s2];
            __syncthreads();
        }
        if (tid == 0) out[2*N_TOKENS] = red[0] * (0.001f / (float)BATCH);
        #pragma unroll
        for (int i = tid; i < BATCH*NEXP; i += TPB) { g_ssum[i] = 0.0f; g_cnt[i] = 0; }
        if (tid == 0) g_done = 0u;
    }
}

extern "C" void kernel_launch(void* const* d_in, const int* in_sizes, int n_in,
                              void* d_out, int out_size) {
    const float* hs = (const float*)d_in[0];
    const float* w  = (const float*)d_in[1];
    float* out = (float*)d_out;
    cudaFuncSetAttribute(gate_kernel, cudaFuncAttributeMaxDynamicSharedMemorySize, SMEM_DYN);
    gate_kernel<<<NBLK, TPB, SMEM_DYN>>>(hs, w, out);
}